// round 14
// baseline (speedup 1.0000x reference)
#include <cuda_runtime.h>
#include <cuda_bf16.h>
#include <cstdint>

constexpr int Bsz = 512, Lz = 128, Hd = 1024, Od = 64, Sq = 256;
constexpr int G4 = 4096, IN0 = 192;
constexpr int KB0 = Od + Hd;      // 1088 = 17*64  (layer0 base K)
constexpr int KB1 = 2 * Hd;       // 2048 = 32*64  (layer1 base K)
constexpr size_t BH = (size_t)Bsz * Hd;

constexpr int BK = 64;
constexpr int ROWB = 144;                 // 128B data + 16B pad
constexpr int R1 = 128 * ROWB;            // one 128-row region: 18432 B
constexpr int STG = 4 * R1;               // Ah | Al | Wh | Wl : 73728 B
constexpr int SMEM_TOTAL = 2 * STG;       // 147456 B, 1 CTA/SM

// ---------------- device scratch ----------------
__device__ __align__(1024) __nv_bfloat16 g_W0h[(size_t)G4 * KB0];
__device__ __align__(1024) __nv_bfloat16 g_W0l[(size_t)G4 * KB0];
__device__ __align__(1024) __nv_bfloat16 g_W1h[(size_t)G4 * KB1];
__device__ __align__(1024) __nv_bfloat16 g_W1l[(size_t)G4 * KB1];
__device__ __align__(1024) __nv_bfloat16 g_P0h[2][(size_t)Bsz * KB0];  // [fb | h1]
__device__ __align__(1024) __nv_bfloat16 g_P0l[2][(size_t)Bsz * KB0];
__device__ __align__(1024) __nv_bfloat16 g_P1h[2][(size_t)Bsz * KB1];  // [h1n | h2]
__device__ __align__(1024) __nv_bfloat16 g_P1l[2][(size_t)Bsz * KB1];
__device__ float g_Wzp[(size_t)G4 * Lz];
__device__ float g_b0p[G4];
__device__ float g_b1p[G4];
__device__ float g_Gzp[(size_t)Bsz * G4];
__device__ float g_cT1[BH];     // c state transposed [k][b]
__device__ float g_cT2[BH];
__device__ float g_h2f[BH];

__device__ __forceinline__ float fsig(float x) { return 1.f / (1.f + __expf(-x)); }
__device__ __forceinline__ float ftanh(float x) {
    float e = __expf(2.f * x);
    return (e - 1.f) * (1.f / (e + 1.f));
}

__device__ __forceinline__ uint32_t s2u(const void* p) {
    uint32_t a;
    asm("{ .reg .u64 t; cvta.to.shared.u64 t, %1; cvt.u32.u64 %0, t; }" : "=r"(a) : "l"(p));
    return a;
}
__device__ __forceinline__ void cp16(uint32_t d, const void* s) {
    asm volatile("cp.async.cg.shared.global [%0], [%1], 16;" :: "r"(d), "l"(s) : "memory");
}
__device__ __forceinline__ void cp_commit() { asm volatile("cp.async.commit_group;" ::: "memory"); }
__device__ __forceinline__ void cp_wait0()  { asm volatile("cp.async.wait_group 0;" ::: "memory"); }

__device__ __forceinline__ void ldsm4(uint32_t* r, uint32_t addr) {
    asm volatile("ldmatrix.sync.aligned.m8n8.x4.shared.b16 {%0,%1,%2,%3}, [%4];"
                 : "=r"(r[0]), "=r"(r[1]), "=r"(r[2]), "=r"(r[3]) : "r"(addr));
}
__device__ __forceinline__ void mma16816(float* c, const uint32_t* a, const uint32_t* b) {
    asm volatile(
        "mma.sync.aligned.m16n8k16.row.col.f32.bf16.bf16.f32 "
        "{%0,%1,%2,%3}, {%4,%5,%6,%7}, {%8,%9}, {%0,%1,%2,%3};"
        : "+f"(c[0]), "+f"(c[1]), "+f"(c[2]), "+f"(c[3])
        : "r"(a[0]), "r"(a[1]), "r"(a[2]), "r"(a[3]), "r"(b[0]), "r"(b[1]));
}

// ---------------- prepass: permute(g*H+k -> 4k+g) + bf16 hi/lo split ----------------
__global__ void pack_weights(const float* __restrict__ Wih0, const float* __restrict__ Whh0,
                             const float* __restrict__ bih0, const float* __restrict__ bhh0,
                             const float* __restrict__ Wih1, const float* __restrict__ Whh1,
                             const float* __restrict__ bih1, const float* __restrict__ bhh1)
{
    int n = blockIdx.x, k = n >> 2, g = n & 3, src = g * Hd + k;
    for (int j = threadIdx.x; j < KB0; j += 256) {
        float w = (j < Od) ? Wih0[(size_t)src * IN0 + Lz + j] : Whh0[(size_t)src * Hd + (j - Od)];
        __nv_bfloat16 h = __float2bfloat16(w);
        g_W0h[(size_t)n * KB0 + j] = h;
        g_W0l[(size_t)n * KB0 + j] = __float2bfloat16(w - __bfloat162float(h));
    }
    for (int j = threadIdx.x; j < KB1; j += 256) {
        float w = (j < Hd) ? Wih1[(size_t)src * Hd + j] : Whh1[(size_t)src * Hd + (j - Hd)];
        __nv_bfloat16 h = __float2bfloat16(w);
        g_W1h[(size_t)n * KB1 + j] = h;
        g_W1l[(size_t)n * KB1 + j] = __float2bfloat16(w - __bfloat162float(h));
    }
    for (int j = threadIdx.x; j < Lz; j += 256)
        g_Wzp[(size_t)n * Lz + j] = Wih0[(size_t)src * IN0 + j];
    if (threadIdx.x == 0) {
        g_b0p[n] = bih0[src] + bhh0[src];
        g_b1p[n] = bih1[src] + bhh1[src];
    }
}

// ---------------- init: h0/c0 projections -> panels / cT; zero fb slots ----------------
__global__ void init_hc(const float* __restrict__ z,
                        const float* __restrict__ Wh, const float* __restrict__ bh,
                        const float* __restrict__ Wc, const float* __restrict__ bc)
{
    __shared__ float zs[8 * Lz];
    int b0 = blockIdx.y * 8;
    for (int i = threadIdx.x; i < 8 * Lz / 4; i += 128)
        ((float4*)zs)[i] = ((const float4*)(z + (size_t)b0 * Lz))[i];
    __syncthreads();
    int k = blockIdx.x * 128 + threadIdx.x;
    const float4* wh = (const float4*)(Wh + (size_t)k * Lz);
    const float4* wc = (const float4*)(Wc + (size_t)k * Lz);
    float ah[8] = {0}, ac[8] = {0};
#pragma unroll 8
    for (int l = 0; l < Lz / 4; ++l) {
        float4 wv = wh[l], cv = wc[l];
#pragma unroll
        for (int r = 0; r < 8; ++r) {
            float4 zv = ((float4*)zs)[r * (Lz / 4) + l];
            ah[r] += zv.x * wv.x + zv.y * wv.y + zv.z * wv.z + zv.w * wv.w;
            ac[r] += zv.x * cv.x + zv.y * cv.y + zv.z * cv.z + zv.w * cv.w;
        }
    }
    float bhv = bh[k], bcv = bc[k];
#pragma unroll
    for (int r = 0; r < 8; ++r) {
        int b = b0 + r;
        float hv = ah[r] + bhv, cv = ac[r] + bcv;
        g_cT1[(size_t)k * Bsz + b] = cv;
        g_cT2[(size_t)k * Bsz + b] = cv;
        __nv_bfloat16 hh = __float2bfloat16(hv);
        __nv_bfloat16 hl = __float2bfloat16(hv - __bfloat162float(hh));
        g_P0h[0][(size_t)b * KB0 + Od + k] = hh;           // h1 slot of layer0 panel
        g_P0l[0][(size_t)b * KB0 + Od + k] = hl;
        g_P1h[0][(size_t)b * KB1 + Hd + k] = hh;           // h2 slot of layer1 panel
        g_P1l[0][(size_t)b * KB1 + Hd + k] = hl;
    }
    if (blockIdx.x == 0 && threadIdx.x < 64) {
        int o = threadIdx.x;
        __nv_bfloat16 zz = __float2bfloat16(0.f);
#pragma unroll
        for (int r = 0; r < 8; ++r) {
            int b = b0 + r;
            g_P0h[0][(size_t)b * KB0 + o] = zz;            // t=0 feedback = 0
            g_P0l[0][(size_t)b * KB0 + o] = zz;
        }
    }
}

// ---------------- Gzp = z @ Wzp.T + b0p (fp32, exact, step-invariant) ----------------
__global__ void gz_gemm(const float* __restrict__ z)
{
    __shared__ float zs[8 * Lz];
    int b0 = blockIdx.y * 8;
    for (int i = threadIdx.x; i < 8 * Lz / 4; i += 128)
        ((float4*)zs)[i] = ((const float4*)(z + (size_t)b0 * Lz))[i];
    __syncthreads();
    int n = blockIdx.x * 128 + threadIdx.x;
    const float4* w = (const float4*)(g_Wzp + (size_t)n * Lz);
    float acc[8] = {0};
#pragma unroll 8
    for (int l = 0; l < Lz / 4; ++l) {
        float4 wv = w[l];
#pragma unroll
        for (int r = 0; r < 8; ++r) {
            float4 zv = ((float4*)zs)[r * (Lz / 4) + l];
            acc[r] += zv.x * wv.x + zv.y * wv.y + zv.z * wv.z + zv.w * wv.w;
        }
    }
    float bb = g_b0p[n];
#pragma unroll
    for (int r = 0; r < 8; ++r)
        g_Gzp[(size_t)(b0 + r) * G4 + n] = acc[r] + bb;
}

// ---------------- dedup 3-pass HMMA GEMM (128x128, BK=64) + fused LSTM epilogue ----------------
// acc = Ah@Wh + Ah@Wl + Al@Wh  (AlWl dropped; ~2^-17 relative)
struct EpiDst { __nv_bfloat16 *hi, *lo; int stride; };

__global__ __launch_bounds__(256) void lstm_mma(
    const __nv_bfloat16* __restrict__ actH, const __nv_bfloat16* __restrict__ actL,
    int K, int nch,
    const __nv_bfloat16* __restrict__ WH, const __nv_bfloat16* __restrict__ WL,
    const float* __restrict__ initT, const float* __restrict__ bias,
    float* __restrict__ cT,
    EpiDst e0, EpiDst e1, float* __restrict__ h32)
{
    extern __shared__ char smem[];
    uint32_t sbase = s2u(smem);
    int tid = threadIdx.x;
    int n0 = blockIdx.x * 128, m0 = blockIdx.y * 128;
    int warp = tid >> 5, lane = tid & 31;
    int wm = warp >> 1, wn = warp & 1;      // 4 x 2 warp grid, warp tile 32 x 64
    int gid = lane >> 2, tid2 = lane & 3;

    float acc[2][8][4];
#pragma unroll
    for (int mi = 0; mi < 2; ++mi)
#pragma unroll
        for (int nj = 0; nj < 8; ++nj)
#pragma unroll
            for (int q = 0; q < 4; ++q) acc[mi][nj][q] = 0.f;

    const __nv_bfloat16* ah = actH + (size_t)m0 * K;
    const __nv_bfloat16* al = actL + (size_t)m0 * K;
    const __nv_bfloat16* wh = WH + (size_t)n0 * K;
    const __nv_bfloat16* wl = WL + (size_t)n0 * K;

    // ldmatrix per-lane base offsets (bytes within a 128-row region) — validated
    uint32_t aOff = (uint32_t)(wm * 32 + (lane & 15)) * ROWB + ((lane >> 4) * 16);
    uint32_t bOff = (uint32_t)(wn * 64 + (lane & 7) + ((lane >> 4) * 8)) * ROWB
                  + (((lane >> 3) & 1) * 16);

    int ldRow = tid >> 3, ldGrp = tid & 7;   // 32 rows per pass over 128-row region
    uint32_t ldDst = (uint32_t)ldRow * ROWB + ldGrp * 16;

#define LOAD_REG(PTR, REG, ST, CH)                                                \
        _Pragma("unroll")                                                         \
        for (int j = 0; j < 4; ++j) {                                             \
            int row = ldRow + 32 * j;                                             \
            cp16((ST) + (REG) * R1 + ldDst + j * 32 * ROWB,                       \
                 (PTR) + (size_t)row * K + (CH) * BK + ldGrp * 8);                \
        }
#define LOAD_CHUNK(CH, BUF) {                                                     \
        uint32_t st = sbase + (BUF) * STG;                                        \
        LOAD_REG(ah, 0, st, CH) LOAD_REG(al, 1, st, CH)                           \
        LOAD_REG(wh, 2, st, CH) LOAD_REG(wl, 3, st, CH)                           \
        cp_commit();                                                              \
    }

    LOAD_CHUNK(0, 0)
    for (int ch = 0; ch < nch; ++ch) {
        int buf = ch & 1;
        cp_wait0();
        __syncthreads();
        if (ch + 1 < nch) LOAD_CHUNK(ch + 1, buf ^ 1)

        uint32_t st = sbase + buf * STG;
#pragma unroll
        for (int p = 0; p < 3; ++p) {
            uint32_t aB = st + (p == 2 ? R1 : 0) + aOff;             // Ah,Ah,Al
            uint32_t bB = st + 2 * R1 + (p == 1 ? R1 : 0) + bOff;    // Wh,Wl,Wh
#pragma unroll
            for (int ks = 0; ks < 4; ++ks) {
                uint32_t Af[2][4], Bf[4][4];
#pragma unroll
                for (int mi = 0; mi < 2; ++mi) ldsm4(Af[mi], aB + mi * 16 * ROWB + ks * 32);
#pragma unroll
                for (int q = 0; q < 4; ++q)    ldsm4(Bf[q], bB + q * 16 * ROWB + ks * 32);
#pragma unroll
                for (int mi = 0; mi < 2; ++mi)
#pragma unroll
                    for (int q = 0; q < 4; ++q) {
                        mma16816(acc[mi][2 * q],     Af[mi], &Bf[q][0]);
                        mma16816(acc[mi][2 * q + 1], Af[mi], &Bf[q][2]);
                    }
            }
        }
    }
#undef LOAD_CHUNK
#undef LOAD_REG
    __syncthreads();   // all ldsm done before smem reuse below

    // ---- epilogue: 4 passes of 128 rows x 32 gate cols through SMEM ----
    float* gbuf = (float*)smem;
    const int GP = 36;
    for (int nq = 0; nq < 4; ++nq) {
        if (wn == (nq >> 1)) {
#pragma unroll
            for (int mi = 0; mi < 2; ++mi)
#pragma unroll
                for (int jj = 0; jj < 4; ++jj) {
                    int nj = (nq & 1) * 4 + jj;
                    int r = wm * 32 + mi * 16 + gid;
                    int cl = jj * 8 + tid2 * 2;
                    gbuf[r * GP + cl]           = acc[mi][nj][0];
                    gbuf[r * GP + cl + 1]       = acc[mi][nj][1];
                    gbuf[(r + 8) * GP + cl]     = acc[mi][nj][2];
                    gbuf[(r + 8) * GP + cl + 1] = acc[mi][nj][3];
                }
        }
        __syncthreads();
#pragma unroll
        for (int idx = tid; idx < 1024; idx += 256) {
            int b = idx >> 3, g = idx & 7;
            int bg = m0 + b;
            float4 a4 = *(const float4*)&gbuf[b * GP + g * 4];
            float4 bb = initT
                ? *(const float4*)(initT + (size_t)bg * G4 + n0 + nq * 32 + g * 4)
                : *(const float4*)(bias + n0 + nq * 32 + g * 4);
            float i_ = fsig(a4.x + bb.x);
            float f_ = fsig(a4.y + bb.y);
            float g_ = ftanh(a4.z + bb.z);
            float o_ = fsig(a4.w + bb.w);
            int k = (n0 >> 2) + nq * 8 + g;
            float c = cT[(size_t)k * Bsz + bg];
            float cn = f_ * c + i_ * g_;
            cT[(size_t)k * Bsz + bg] = cn;
            float h = o_ * ftanh(cn);
            __nv_bfloat16 hh = __float2bfloat16(h);
            __nv_bfloat16 hl = __float2bfloat16(h - __bfloat162float(hh));
            e0.hi[(size_t)bg * e0.stride + k] = hh;
            e0.lo[(size_t)bg * e0.stride + k] = hl;
            if (e1.hi) {
                e1.hi[(size_t)bg * e1.stride + k] = hh;
                e1.lo[(size_t)bg * e1.stride + k] = hl;
            }
            if (h32) h32[(size_t)bg * Hd + k] = h;
        }
        __syncthreads();
    }
}

// ---------------- out = h2 @ Wout.T + bout -> d_out[:,t,:] + bf16 feedback ----------------
__global__ void out_proj(const float* __restrict__ h2, const float* __restrict__ Wout,
                         const float* __restrict__ bout, float* __restrict__ dout, int t,
                         __nv_bfloat16* __restrict__ PnH, __nv_bfloat16* __restrict__ PnL)
{
    __shared__ float hs[Hd];
    int b = blockIdx.x, o = threadIdx.x;
    for (int i = o; i < Hd / 4; i += 64)
        ((float4*)hs)[i] = ((const float4*)(h2 + (size_t)b * Hd))[i];
    __syncthreads();
    const float4* w = (const float4*)(Wout + (size_t)o * Hd);
    float acc = 0.f;
#pragma unroll 8
    for (int i = 0; i < Hd / 4; ++i) {
        float4 wv = w[i], hv = ((float4*)hs)[i];
        acc += wv.x * hv.x + wv.y * hv.y + wv.z * hv.z + wv.w * hv.w;
    }
    acc += bout[o];
    __nv_bfloat16 hh = __float2bfloat16(acc);
    PnH[(size_t)b * KB0 + o] = hh;
    PnL[(size_t)b * KB0 + o] = __float2bfloat16(acc - __bfloat162float(hh));
    dout[(size_t)b * Sq * Od + (size_t)t * Od + o] = acc;
}

// ---------------- host ----------------
extern "C" void kernel_launch(void* const* d_in, const int* in_sizes, int n_in,
                              void* d_out, int out_size)
{
    const float* z    = (const float*)d_in[0];
    const float* Wh   = (const float*)d_in[1];
    const float* bh   = (const float*)d_in[2];
    const float* Wc   = (const float*)d_in[3];
    const float* bc   = (const float*)d_in[4];
    const float* Wih0 = (const float*)d_in[5];
    const float* Whh0 = (const float*)d_in[6];
    const float* bih0 = (const float*)d_in[7];
    const float* bhh0 = (const float*)d_in[8];
    const float* Wih1 = (const float*)d_in[9];
    const float* Whh1 = (const float*)d_in[10];
    const float* bih1 = (const float*)d_in[11];
    const float* bhh1 = (const float*)d_in[12];
    const float* Wout = (const float*)d_in[13];
    const float* bout = (const float*)d_in[14];
    float* out = (float*)d_out;

    __nv_bfloat16 *p_W0h, *p_W0l, *p_W1h, *p_W1l, *p_P0h, *p_P0l, *p_P1h, *p_P1l;
    float *p_Gzp, *p_b1p, *p_cT1, *p_cT2, *p_h2f;
    cudaGetSymbolAddress((void**)&p_W0h, g_W0h);
    cudaGetSymbolAddress((void**)&p_W0l, g_W0l);
    cudaGetSymbolAddress((void**)&p_W1h, g_W1h);
    cudaGetSymbolAddress((void**)&p_W1l, g_W1l);
    cudaGetSymbolAddress((void**)&p_P0h, g_P0h);
    cudaGetSymbolAddress((void**)&p_P0l, g_P0l);
    cudaGetSymbolAddress((void**)&p_P1h, g_P1h);
    cudaGetSymbolAddress((void**)&p_P1l, g_P1l);
    cudaGetSymbolAddress((void**)&p_Gzp, g_Gzp);
    cudaGetSymbolAddress((void**)&p_b1p, g_b1p);
    cudaGetSymbolAddress((void**)&p_cT1, g_cT1);
    cudaGetSymbolAddress((void**)&p_cT2, g_cT2);
    cudaGetSymbolAddress((void**)&p_h2f, g_h2f);

    cudaFuncSetAttribute(lstm_mma, cudaFuncAttributeMaxDynamicSharedMemorySize, SMEM_TOTAL);

    pack_weights<<<G4, 256>>>(Wih0, Whh0, bih0, bhh0, Wih1, Whh1, bih1, bhh1);
    init_hc<<<dim3(Hd / 128, Bsz / 8), 128>>>(z, Wh, bh, Wc, bc);
    gz_gemm<<<dim3(G4 / 128, Bsz / 8), 128>>>(z);

    dim3 gg(G4 / 128, Bsz / 128);     // 32 x 4 = 128 CTAs
    const size_t P0sz = (size_t)Bsz * KB0, P1sz = (size_t)Bsz * KB1;
    for (int t = 0; t < Sq; ++t) {
        int cur = t & 1, nxt = cur ^ 1;
        __nv_bfloat16 *P0hc = p_P0h + cur * P0sz, *P0lc = p_P0l + cur * P0sz;
        __nv_bfloat16 *P0hn = p_P0h + nxt * P0sz, *P0ln = p_P0l + nxt * P0sz;
        __nv_bfloat16 *P1hc = p_P1h + cur * P1sz, *P1lc = p_P1l + cur * P1sz;
        __nv_bfloat16 *P1hn = p_P1h + nxt * P1sz, *P1ln = p_P1l + nxt * P1sz;

        // layer 0: gates = Gzp + [fb h1] @ W0.T  (3-term split in-kernel)
        EpiDst e0{P1hc + 0, P1lc + 0, KB1};        // h1n -> layer1 panel (this step)
        EpiDst e1{P0hn + Od, P0ln + Od, KB0};      // h1n -> layer0 panel (next step)
        lstm_mma<<<gg, 256, SMEM_TOTAL>>>(P0hc, P0lc, KB0, KB0 / BK, p_W0h, p_W0l,
                                          p_Gzp, nullptr, p_cT1, e0, e1, nullptr);

        // layer 1: gates = b1p + [h1n h2] @ W1.T
        EpiDst f0{P1hn + Hd, P1ln + Hd, KB1};      // h2 -> layer1 panel (next step)
        EpiDst f1{nullptr, nullptr, 0};
        lstm_mma<<<gg, 256, SMEM_TOTAL>>>(P1hc, P1lc, KB1, KB1 / BK, p_W1h, p_W1l,
                                          nullptr, p_b1p, p_cT2, f0, f1, p_h2f);

        out_proj<<<Bsz, 64>>>(p_h2f, Wout, bout, out, t, P0hn, P0ln);
    }
}

// round 15
// speedup vs baseline: 1.0984x; 1.0984x over previous
#include <cuda_runtime.h>
#include <cuda_bf16.h>
#include <cstdint>

constexpr int Bsz = 512, Lz = 128, Hd = 1024, Od = 64, Sq = 256;
constexpr int G4 = 4096, IN0 = 192;
constexpr int KB0 = Od + Hd;      // 1088 = 17*64  (layer0 base K)
constexpr int KB1 = 2 * Hd;       // 2048 = 32*64  (layer1 base K)
constexpr size_t BH = (size_t)Bsz * Hd;

constexpr int BK = 64;
constexpr int ROWB = 144;                 // 128B data + 16B pad
constexpr int RA = 128 * ROWB;            // A region: 18432 B
constexpr int RB = 64 * ROWB;             // W region: 9216 B
constexpr int OFF_AL = RA;                // Al
constexpr int OFF_WH = 2 * RA;            // Wh
constexpr int OFF_WL = 2 * RA + RB;       // Wl
constexpr int STG = 2 * RA + 2 * RB;      // 55296 B per stage
constexpr int SMEM_TOTAL = 2 * STG;       // 110592 B -> 2 CTAs/SM

// ---------------- device scratch ----------------
__device__ __align__(1024) __nv_bfloat16 g_W0h[(size_t)G4 * KB0];
__device__ __align__(1024) __nv_bfloat16 g_W0l[(size_t)G4 * KB0];
__device__ __align__(1024) __nv_bfloat16 g_W1h[(size_t)G4 * KB1];
__device__ __align__(1024) __nv_bfloat16 g_W1l[(size_t)G4 * KB1];
__device__ __align__(1024) __nv_bfloat16 g_P0h[2][(size_t)Bsz * KB0];  // [fb | h1]
__device__ __align__(1024) __nv_bfloat16 g_P0l[2][(size_t)Bsz * KB0];
__device__ __align__(1024) __nv_bfloat16 g_P1h[2][(size_t)Bsz * KB1];  // [h1n | h2]
__device__ __align__(1024) __nv_bfloat16 g_P1l[2][(size_t)Bsz * KB1];
__device__ float g_Wzp[(size_t)G4 * Lz];
__device__ float g_b0p[G4];
__device__ float g_b1p[G4];
__device__ float g_Gzp[(size_t)Bsz * G4];
__device__ float g_cT1[BH];     // c state transposed [k][b]
__device__ float g_cT2[BH];
__device__ float g_h2f[BH];

__device__ __forceinline__ float fsig(float x) { return 1.f / (1.f + __expf(-x)); }
__device__ __forceinline__ float ftanh(float x) {
    float e = __expf(2.f * x);
    return (e - 1.f) * (1.f / (e + 1.f));
}

__device__ __forceinline__ uint32_t s2u(const void* p) {
    uint32_t a;
    asm("{ .reg .u64 t; cvta.to.shared.u64 t, %1; cvt.u32.u64 %0, t; }" : "=r"(a) : "l"(p));
    return a;
}
__device__ __forceinline__ void cp16(uint32_t d, const void* s) {
    asm volatile("cp.async.cg.shared.global [%0], [%1], 16;" :: "r"(d), "l"(s) : "memory");
}
__device__ __forceinline__ void cp_commit() { asm volatile("cp.async.commit_group;" ::: "memory"); }
__device__ __forceinline__ void cp_wait0()  { asm volatile("cp.async.wait_group 0;" ::: "memory"); }

__device__ __forceinline__ void ldsm4(uint32_t* r, uint32_t addr) {
    asm volatile("ldmatrix.sync.aligned.m8n8.x4.shared.b16 {%0,%1,%2,%3}, [%4];"
                 : "=r"(r[0]), "=r"(r[1]), "=r"(r[2]), "=r"(r[3]) : "r"(addr));
}
__device__ __forceinline__ void mma16816(float* c, const uint32_t* a, const uint32_t* b) {
    asm volatile(
        "mma.sync.aligned.m16n8k16.row.col.f32.bf16.bf16.f32 "
        "{%0,%1,%2,%3}, {%4,%5,%6,%7}, {%8,%9}, {%0,%1,%2,%3};"
        : "+f"(c[0]), "+f"(c[1]), "+f"(c[2]), "+f"(c[3])
        : "r"(a[0]), "r"(a[1]), "r"(a[2]), "r"(a[3]), "r"(b[0]), "r"(b[1]));
}

// ---------------- prepass: permute(g*H+k -> 4k+g) + bf16 hi/lo split ----------------
__global__ void pack_weights(const float* __restrict__ Wih0, const float* __restrict__ Whh0,
                             const float* __restrict__ bih0, const float* __restrict__ bhh0,
                             const float* __restrict__ Wih1, const float* __restrict__ Whh1,
                             const float* __restrict__ bih1, const float* __restrict__ bhh1)
{
    int n = blockIdx.x, k = n >> 2, g = n & 3, src = g * Hd + k;
    for (int j = threadIdx.x; j < KB0; j += 256) {
        float w = (j < Od) ? Wih0[(size_t)src * IN0 + Lz + j] : Whh0[(size_t)src * Hd + (j - Od)];
        __nv_bfloat16 h = __float2bfloat16(w);
        g_W0h[(size_t)n * KB0 + j] = h;
        g_W0l[(size_t)n * KB0 + j] = __float2bfloat16(w - __bfloat162float(h));
    }
    for (int j = threadIdx.x; j < KB1; j += 256) {
        float w = (j < Hd) ? Wih1[(size_t)src * Hd + j] : Whh1[(size_t)src * Hd + (j - Hd)];
        __nv_bfloat16 h = __float2bfloat16(w);
        g_W1h[(size_t)n * KB1 + j] = h;
        g_W1l[(size_t)n * KB1 + j] = __float2bfloat16(w - __bfloat162float(h));
    }
    for (int j = threadIdx.x; j < Lz; j += 256)
        g_Wzp[(size_t)n * Lz + j] = Wih0[(size_t)src * IN0 + j];
    if (threadIdx.x == 0) {
        g_b0p[n] = bih0[src] + bhh0[src];
        g_b1p[n] = bih1[src] + bhh1[src];
    }
}

// ---------------- init: h0/c0 projections -> panels / cT; zero fb slots ----------------
__global__ void init_hc(const float* __restrict__ z,
                        const float* __restrict__ Wh, const float* __restrict__ bh,
                        const float* __restrict__ Wc, const float* __restrict__ bc)
{
    __shared__ float zs[8 * Lz];
    int b0 = blockIdx.y * 8;
    for (int i = threadIdx.x; i < 8 * Lz / 4; i += 128)
        ((float4*)zs)[i] = ((const float4*)(z + (size_t)b0 * Lz))[i];
    __syncthreads();
    int k = blockIdx.x * 128 + threadIdx.x;
    const float4* wh = (const float4*)(Wh + (size_t)k * Lz);
    const float4* wc = (const float4*)(Wc + (size_t)k * Lz);
    float ah[8] = {0}, ac[8] = {0};
#pragma unroll 8
    for (int l = 0; l < Lz / 4; ++l) {
        float4 wv = wh[l], cv = wc[l];
#pragma unroll
        for (int r = 0; r < 8; ++r) {
            float4 zv = ((float4*)zs)[r * (Lz / 4) + l];
            ah[r] += zv.x * wv.x + zv.y * wv.y + zv.z * wv.z + zv.w * wv.w;
            ac[r] += zv.x * cv.x + zv.y * cv.y + zv.z * cv.z + zv.w * cv.w;
        }
    }
    float bhv = bh[k], bcv = bc[k];
#pragma unroll
    for (int r = 0; r < 8; ++r) {
        int b = b0 + r;
        float hv = ah[r] + bhv, cv = ac[r] + bcv;
        g_cT1[(size_t)k * Bsz + b] = cv;
        g_cT2[(size_t)k * Bsz + b] = cv;
        __nv_bfloat16 hh = __float2bfloat16(hv);
        __nv_bfloat16 hl = __float2bfloat16(hv - __bfloat162float(hh));
        g_P0h[0][(size_t)b * KB0 + Od + k] = hh;
        g_P0l[0][(size_t)b * KB0 + Od + k] = hl;
        g_P1h[0][(size_t)b * KB1 + Hd + k] = hh;
        g_P1l[0][(size_t)b * KB1 + Hd + k] = hl;
    }
    if (blockIdx.x == 0 && threadIdx.x < 64) {
        int o = threadIdx.x;
        __nv_bfloat16 zz = __float2bfloat16(0.f);
#pragma unroll
        for (int r = 0; r < 8; ++r) {
            int b = b0 + r;
            g_P0h[0][(size_t)b * KB0 + o] = zz;
            g_P0l[0][(size_t)b * KB0 + o] = zz;
        }
    }
}

// ---------------- Gzp = z @ Wzp.T + b0p (fp32, exact, step-invariant) ----------------
__global__ void gz_gemm(const float* __restrict__ z)
{
    __shared__ float zs[8 * Lz];
    int b0 = blockIdx.y * 8;
    for (int i = threadIdx.x; i < 8 * Lz / 4; i += 128)
        ((float4*)zs)[i] = ((const float4*)(z + (size_t)b0 * Lz))[i];
    __syncthreads();
    int n = blockIdx.x * 128 + threadIdx.x;
    const float4* w = (const float4*)(g_Wzp + (size_t)n * Lz);
    float acc[8] = {0};
#pragma unroll 8
    for (int l = 0; l < Lz / 4; ++l) {
        float4 wv = w[l];
#pragma unroll
        for (int r = 0; r < 8; ++r) {
            float4 zv = ((float4*)zs)[r * (Lz / 4) + l];
            acc[r] += zv.x * wv.x + zv.y * wv.y + zv.z * wv.z + zv.w * wv.w;
        }
    }
    float bb = g_b0p[n];
#pragma unroll
    for (int r = 0; r < 8; ++r)
        g_Gzp[(size_t)(b0 + r) * G4 + n] = acc[r] + bb;
}

// ---------------- dedup 3-pass HMMA GEMM (128x64, BK=64, 256 CTAs) + LSTM epilogue ----------------
// acc = Ah@Wh + Ah@Wl + Al@Wh   (AlWl dropped; ~2^-17 relative)
struct EpiDst { __nv_bfloat16 *hi, *lo; int stride; };

__global__ __launch_bounds__(256) void lstm_mma(
    const __nv_bfloat16* __restrict__ actH, const __nv_bfloat16* __restrict__ actL,
    int K, int nch,
    const __nv_bfloat16* __restrict__ WH, const __nv_bfloat16* __restrict__ WL,
    const float* __restrict__ initT, const float* __restrict__ bias,
    float* __restrict__ cT,
    EpiDst e0, EpiDst e1, float* __restrict__ h32)
{
    extern __shared__ char smem[];
    uint32_t sbase = s2u(smem);
    int tid = threadIdx.x;
    int n0 = blockIdx.x * 64, m0 = blockIdx.y * 128;
    int warp = tid >> 5, lane = tid & 31;
    int wm = warp >> 1, wn = warp & 1;      // 4 x 2 warp grid, warp tile 32 x 32
    int gid = lane >> 2, tid2 = lane & 3;

    float acc[2][4][4];
#pragma unroll
    for (int mi = 0; mi < 2; ++mi)
#pragma unroll
        for (int nj = 0; nj < 4; ++nj)
#pragma unroll
            for (int q = 0; q < 4; ++q) acc[mi][nj][q] = 0.f;

    const __nv_bfloat16* ah = actH + (size_t)m0 * K;
    const __nv_bfloat16* al = actL + (size_t)m0 * K;
    const __nv_bfloat16* wh = WH + (size_t)n0 * K;
    const __nv_bfloat16* wl = WL + (size_t)n0 * K;

    // ldmatrix per-lane base offsets (bytes within a region) — validated mapping
    uint32_t aOff = (uint32_t)(wm * 32 + (lane & 15)) * ROWB + ((lane >> 4) * 16);
    uint32_t bOff = (uint32_t)(wn * 32 + (lane & 7) + ((lane >> 4) * 8)) * ROWB
                  + (((lane >> 3) & 1) * 16);

    int ldRow = tid >> 3, ldGrp = tid & 7;   // 32 rows per pass
    uint32_t ldDst = (uint32_t)ldRow * ROWB + ldGrp * 16;

#define LOAD_CHUNK(CH, BUF) {                                                     \
        uint32_t st = sbase + (BUF) * STG;                                        \
        const __nv_bfloat16* pah = ah + (CH) * BK + ldGrp * 8;                    \
        const __nv_bfloat16* pal = al + (CH) * BK + ldGrp * 8;                    \
        const __nv_bfloat16* pwh = wh + (CH) * BK + ldGrp * 8;                    \
        const __nv_bfloat16* pwl = wl + (CH) * BK + ldGrp * 8;                    \
        _Pragma("unroll")                                                         \
        for (int j = 0; j < 4; ++j) {                                             \
            int row = ldRow + 32 * j;                                             \
            cp16(st + ldDst + j * 32 * ROWB, pah + (size_t)row * K);              \
            cp16(st + OFF_AL + ldDst + j * 32 * ROWB, pal + (size_t)row * K);     \
        }                                                                         \
        _Pragma("unroll")                                                         \
        for (int j = 0; j < 2; ++j) {                                             \
            int row = ldRow + 32 * j;                                             \
            cp16(st + OFF_WH + ldDst + j * 32 * ROWB, pwh + (size_t)row * K);     \
            cp16(st + OFF_WL + ldDst + j * 32 * ROWB, pwl + (size_t)row * K);     \
        }                                                                         \
        cp_commit();                                                              \
    }

    LOAD_CHUNK(0, 0)
    for (int ch = 0; ch < nch; ++ch) {
        int buf = ch & 1;
        cp_wait0();
        __syncthreads();
        if (ch + 1 < nch) LOAD_CHUNK(ch + 1, buf ^ 1)

        uint32_t st = sbase + buf * STG;
#pragma unroll
        for (int p = 0; p < 3; ++p) {
            uint32_t aB = st + (p == 2 ? OFF_AL : 0u) + aOff;               // Ah,Ah,Al
            uint32_t bB = st + (p == 1 ? OFF_WL : (uint32_t)OFF_WH) + bOff; // Wh,Wl,Wh
#pragma unroll
            for (int ks = 0; ks < 4; ++ks) {
                uint32_t Af[2][4], Bf[2][4];
#pragma unroll
                for (int mi = 0; mi < 2; ++mi) ldsm4(Af[mi], aB + mi * 16 * ROWB + ks * 32);
#pragma unroll
                for (int q = 0; q < 2; ++q)    ldsm4(Bf[q], bB + q * 16 * ROWB + ks * 32);
#pragma unroll
                for (int mi = 0; mi < 2; ++mi)
#pragma unroll
                    for (int q = 0; q < 2; ++q) {
                        mma16816(acc[mi][2 * q],     Af[mi], &Bf[q][0]);
                        mma16816(acc[mi][2 * q + 1], Af[mi], &Bf[q][2]);
                    }
            }
        }
    }
#undef LOAD_CHUNK
    __syncthreads();   // all ldsm done before smem reuse below

    // ---- epilogue: 2 passes of 128 rows x 32 gate cols through SMEM ----
    float* gbuf = (float*)smem;
    const int GP = 36;
    for (int nq = 0; nq < 2; ++nq) {
        if (wn == nq) {
#pragma unroll
            for (int mi = 0; mi < 2; ++mi)
#pragma unroll
                for (int nj = 0; nj < 4; ++nj) {
                    int r = wm * 32 + mi * 16 + gid;
                    int cl = nj * 8 + tid2 * 2;
                    gbuf[r * GP + cl]           = acc[mi][nj][0];
                    gbuf[r * GP + cl + 1]       = acc[mi][nj][1];
                    gbuf[(r + 8) * GP + cl]     = acc[mi][nj][2];
                    gbuf[(r + 8) * GP + cl + 1] = acc[mi][nj][3];
                }
        }
        __syncthreads();
#pragma unroll
        for (int idx = tid; idx < 1024; idx += 256) {
            int b = idx >> 3, g = idx & 7;
            int bg = m0 + b;
            float4 a4 = *(const float4*)&gbuf[b * GP + g * 4];
            float4 bb = initT
                ? *(const float4*)(initT + (size_t)bg * G4 + n0 + nq * 32 + g * 4)
                : *(const float4*)(bias + n0 + nq * 32 + g * 4);
            float i_ = fsig(a4.x + bb.x);
            float f_ = fsig(a4.y + bb.y);
            float g_ = ftanh(a4.z + bb.z);
            float o_ = fsig(a4.w + bb.w);
            int k = (n0 >> 2) + nq * 8 + g;
            float c = cT[(size_t)k * Bsz + bg];
            float cn = f_ * c + i_ * g_;
            cT[(size_t)k * Bsz + bg] = cn;
            float h = o_ * ftanh(cn);
            __nv_bfloat16 hh = __float2bfloat16(h);
            __nv_bfloat16 hl = __float2bfloat16(h - __bfloat162float(hh));
            e0.hi[(size_t)bg * e0.stride + k] = hh;
            e0.lo[(size_t)bg * e0.stride + k] = hl;
            if (e1.hi) {
                e1.hi[(size_t)bg * e1.stride + k] = hh;
                e1.lo[(size_t)bg * e1.stride + k] = hl;
            }
            if (h32) h32[(size_t)bg * Hd + k] = h;
        }
        __syncthreads();
    }
}

// ---------------- out = h2 @ Wout.T + bout -> d_out[:,t,:] + bf16 feedback ----------------
__global__ void out_proj(const float* __restrict__ h2, const float* __restrict__ Wout,
                         const float* __restrict__ bout, float* __restrict__ dout, int t,
                         __nv_bfloat16* __restrict__ PnH, __nv_bfloat16* __restrict__ PnL)
{
    __shared__ float hs[Hd];
    int b = blockIdx.x, o = threadIdx.x;
    for (int i = o; i < Hd / 4; i += 64)
        ((float4*)hs)[i] = ((const float4*)(h2 + (size_t)b * Hd))[i];
    __syncthreads();
    const float4* w = (const float4*)(Wout + (size_t)o * Hd);
    float acc = 0.f;
#pragma unroll 8
    for (int i = 0; i < Hd / 4; ++i) {
        float4 wv = w[i], hv = ((float4*)hs)[i];
        acc += wv.x * hv.x + wv.y * hv.y + wv.z * hv.z + wv.w * hv.w;
    }
    acc += bout[o];
    __nv_bfloat16 hh = __float2bfloat16(acc);
    PnH[(size_t)b * KB0 + o] = hh;
    PnL[(size_t)b * KB0 + o] = __float2bfloat16(acc - __bfloat162float(hh));
    dout[(size_t)b * Sq * Od + (size_t)t * Od + o] = acc;
}

// ---------------- host ----------------
extern "C" void kernel_launch(void* const* d_in, const int* in_sizes, int n_in,
                              void* d_out, int out_size)
{
    const float* z    = (const float*)d_in[0];
    const float* Wh   = (const float*)d_in[1];
    const float* bh   = (const float*)d_in[2];
    const float* Wc   = (const float*)d_in[3];
    const float* bc   = (const float*)d_in[4];
    const float* Wih0 = (const float*)d_in[5];
    const float* Whh0 = (const float*)d_in[6];
    const float* bih0 = (const float*)d_in[7];
    const float* bhh0 = (const float*)d_in[8];
    const float* Wih1 = (const float*)d_in[9];
    const float* Whh1 = (const float*)d_in[10];
    const float* bih1 = (const float*)d_in[11];
    const float* bhh1 = (const float*)d_in[12];
    const float* Wout = (const float*)d_in[13];
    const float* bout = (const float*)d_in[14];
    float* out = (float*)d_out;

    __nv_bfloat16 *p_W0h, *p_W0l, *p_W1h, *p_W1l, *p_P0h, *p_P0l, *p_P1h, *p_P1l;
    float *p_Gzp, *p_b1p, *p_cT1, *p_cT2, *p_h2f;
    cudaGetSymbolAddress((void**)&p_W0h, g_W0h);
    cudaGetSymbolAddress((void**)&p_W0l, g_W0l);
    cudaGetSymbolAddress((void**)&p_W1h, g_W1h);
    cudaGetSymbolAddress((void**)&p_W1l, g_W1l);
    cudaGetSymbolAddress((void**)&p_P0h, g_P0h);
    cudaGetSymbolAddress((void**)&p_P0l, g_P0l);
    cudaGetSymbolAddress((void**)&p_P1h, g_P1h);
    cudaGetSymbolAddress((void**)&p_P1l, g_P1l);
    cudaGetSymbolAddress((void**)&p_Gzp, g_Gzp);
    cudaGetSymbolAddress((void**)&p_b1p, g_b1p);
    cudaGetSymbolAddress((void**)&p_cT1, g_cT1);
    cudaGetSymbolAddress((void**)&p_cT2, g_cT2);
    cudaGetSymbolAddress((void**)&p_h2f, g_h2f);

    cudaFuncSetAttribute(lstm_mma, cudaFuncAttributeMaxDynamicSharedMemorySize, SMEM_TOTAL);

    pack_weights<<<G4, 256>>>(Wih0, Whh0, bih0, bhh0, Wih1, Whh1, bih1, bhh1);
    init_hc<<<dim3(Hd / 128, Bsz / 8), 128>>>(z, Wh, bh, Wc, bc);
    gz_gemm<<<dim3(G4 / 128, Bsz / 8), 128>>>(z);

    dim3 gg(G4 / 64, Bsz / 128);     // 64 x 4 = 256 CTAs
    const size_t P0sz = (size_t)Bsz * KB0, P1sz = (size_t)Bsz * KB1;
    for (int t = 0; t < Sq; ++t) {
        int cur = t & 1, nxt = cur ^ 1;
        __nv_bfloat16 *P0hc = p_P0h + cur * P0sz, *P0lc = p_P0l + cur * P0sz;
        __nv_bfloat16 *P0hn = p_P0h + nxt * P0sz, *P0ln = p_P0l + nxt * P0sz;
        __nv_bfloat16 *P1hc = p_P1h + cur * P1sz, *P1lc = p_P1l + cur * P1sz;
        __nv_bfloat16 *P1hn = p_P1h + nxt * P1sz, *P1ln = p_P1l + nxt * P1sz;

        // layer 0: gates = Gzp + [fb h1] @ W0.T  (3-term split in-kernel)
        EpiDst e0{P1hc + 0, P1lc + 0, KB1};        // h1n -> layer1 panel (this step)
        EpiDst e1{P0hn + Od, P0ln + Od, KB0};      // h1n -> layer0 panel (next step)
        lstm_mma<<<gg, 256, SMEM_TOTAL>>>(P0hc, P0lc, KB0, KB0 / BK, p_W0h, p_W0l,
                                          p_Gzp, nullptr, p_cT1, e0, e1, nullptr);

        // layer 1: gates = b1p + [h1n h2] @ W1.T
        EpiDst f0{P1hn + Hd, P1ln + Hd, KB1};      // h2 -> layer1 panel (next step)
        EpiDst f1{nullptr, nullptr, 0};
        lstm_mma<<<gg, 256, SMEM_TOTAL>>>(P1hc, P1lc, KB1, KB1 / BK, p_W1h, p_W1l,
                                          nullptr, p_b1p, p_cT2, f0, f1, p_h2f);

        out_proj<<<Bsz, 64>>>(p_h2f, Wout, bout, out, t, P0hn, P0ln);
    }
}

// round 16
// speedup vs baseline: 1.3188x; 1.2007x over previous
#include <cuda_runtime.h>
#include <cuda_bf16.h>
#include <cstdint>

constexpr int Bsz = 512, Lz = 128, Hd = 1024, Od = 64, Sq = 256;
constexpr int G4 = 4096, IN0 = 192;
constexpr int KB0 = Od + Hd;      // 1088 = 17*64  (layer0 base K)
constexpr int KB1 = 2 * Hd;       // 2048 = 32*64  (layer1 base K)
constexpr size_t BH = (size_t)Bsz * Hd;

constexpr int BK = 64;
constexpr int ROWB = 144;                 // 128B data + 16B pad
constexpr int RA = 128 * ROWB;            // A region: 18432 B
constexpr int RB = 64 * ROWB;             // W region: 9216 B
constexpr int OFF_AL = RA;                // Al
constexpr int OFF_WH = 2 * RA;            // Wh
constexpr int OFF_WL = 2 * RA + RB;       // Wl
constexpr int STG = 2 * RA + 2 * RB;      // 55296 B per stage
constexpr int SMEM_TOTAL = 2 * STG;       // 110592 B -> 2 CTAs/SM

// ---------------- device scratch ----------------
__device__ __align__(1024) __nv_bfloat16 g_W0h[(size_t)G4 * KB0];
__device__ __align__(1024) __nv_bfloat16 g_W0l[(size_t)G4 * KB0];
__device__ __align__(1024) __nv_bfloat16 g_W1h[(size_t)G4 * KB1];
__device__ __align__(1024) __nv_bfloat16 g_W1l[(size_t)G4 * KB1];
__device__ __align__(1024) __nv_bfloat16 g_P0h[2][(size_t)Bsz * KB0];  // [fb | h1]
__device__ __align__(1024) __nv_bfloat16 g_P0l[2][(size_t)Bsz * KB0];
__device__ __align__(1024) __nv_bfloat16 g_P1h[2][(size_t)Bsz * KB1];  // [h1n | h2]
__device__ __align__(1024) __nv_bfloat16 g_P1l[2][(size_t)Bsz * KB1];
__device__ float g_Wzp[(size_t)G4 * Lz];
__device__ float g_b0p[G4];
__device__ float g_b1p[G4];
__device__ float g_Gzp[(size_t)Bsz * G4];
__device__ float g_cT1[BH];     // c state transposed [k][b]
__device__ float g_cT2[BH];
__device__ float g_h2f[BH];

__device__ __forceinline__ float fsig(float x) { return 1.f / (1.f + __expf(-x)); }
__device__ __forceinline__ float ftanh(float x) {
    float e = __expf(2.f * x);
    return (e - 1.f) * (1.f / (e + 1.f));
}

__device__ __forceinline__ uint32_t s2u(const void* p) {
    uint32_t a;
    asm("{ .reg .u64 t; cvta.to.shared.u64 t, %1; cvt.u32.u64 %0, t; }" : "=r"(a) : "l"(p));
    return a;
}
__device__ __forceinline__ void cp16(uint32_t d, const void* s) {
    asm volatile("cp.async.cg.shared.global [%0], [%1], 16;" :: "r"(d), "l"(s) : "memory");
}
__device__ __forceinline__ void cp_commit() { asm volatile("cp.async.commit_group;" ::: "memory"); }
__device__ __forceinline__ void cp_wait0()  { asm volatile("cp.async.wait_group 0;" ::: "memory"); }

__device__ __forceinline__ void ldsm4(uint32_t* r, uint32_t addr) {
    asm volatile("ldmatrix.sync.aligned.m8n8.x4.shared.b16 {%0,%1,%2,%3}, [%4];"
                 : "=r"(r[0]), "=r"(r[1]), "=r"(r[2]), "=r"(r[3]) : "r"(addr));
}
__device__ __forceinline__ void mma16816(float* c, const uint32_t* a, const uint32_t* b) {
    asm volatile(
        "mma.sync.aligned.m16n8k16.row.col.f32.bf16.bf16.f32 "
        "{%0,%1,%2,%3}, {%4,%5,%6,%7}, {%8,%9}, {%0,%1,%2,%3};"
        : "+f"(c[0]), "+f"(c[1]), "+f"(c[2]), "+f"(c[3])
        : "r"(a[0]), "r"(a[1]), "r"(a[2]), "r"(a[3]), "r"(b[0]), "r"(b[1]));
}

// ---------------- prepass: permute(g*H+k -> 4k+g) + bf16 hi/lo split ----------------
__global__ void pack_weights(const float* __restrict__ Wih0, const float* __restrict__ Whh0,
                             const float* __restrict__ bih0, const float* __restrict__ bhh0,
                             const float* __restrict__ Wih1, const float* __restrict__ Whh1,
                             const float* __restrict__ bih1, const float* __restrict__ bhh1)
{
    int n = blockIdx.x, k = n >> 2, g = n & 3, src = g * Hd + k;
    for (int j = threadIdx.x; j < KB0; j += 256) {
        float w = (j < Od) ? Wih0[(size_t)src * IN0 + Lz + j] : Whh0[(size_t)src * Hd + (j - Od)];
        __nv_bfloat16 h = __float2bfloat16(w);
        g_W0h[(size_t)n * KB0 + j] = h;
        g_W0l[(size_t)n * KB0 + j] = __float2bfloat16(w - __bfloat162float(h));
    }
    for (int j = threadIdx.x; j < KB1; j += 256) {
        float w = (j < Hd) ? Wih1[(size_t)src * Hd + j] : Whh1[(size_t)src * Hd + (j - Hd)];
        __nv_bfloat16 h = __float2bfloat16(w);
        g_W1h[(size_t)n * KB1 + j] = h;
        g_W1l[(size_t)n * KB1 + j] = __float2bfloat16(w - __bfloat162float(h));
    }
    for (int j = threadIdx.x; j < Lz; j += 256)
        g_Wzp[(size_t)n * Lz + j] = Wih0[(size_t)src * IN0 + j];
    if (threadIdx.x == 0) {
        g_b0p[n] = bih0[src] + bhh0[src];
        g_b1p[n] = bih1[src] + bhh1[src];
    }
}

// ---------------- init: h0/c0 projections -> panels / cT; zero fb slots ----------------
__global__ void init_hc(const float* __restrict__ z,
                        const float* __restrict__ Wh, const float* __restrict__ bh,
                        const float* __restrict__ Wc, const float* __restrict__ bc)
{
    __shared__ float zs[8 * Lz];
    int b0 = blockIdx.y * 8;
    for (int i = threadIdx.x; i < 8 * Lz / 4; i += 128)
        ((float4*)zs)[i] = ((const float4*)(z + (size_t)b0 * Lz))[i];
    __syncthreads();
    int k = blockIdx.x * 128 + threadIdx.x;
    const float4* wh = (const float4*)(Wh + (size_t)k * Lz);
    const float4* wc = (const float4*)(Wc + (size_t)k * Lz);
    float ah[8] = {0}, ac[8] = {0};
#pragma unroll 8
    for (int l = 0; l < Lz / 4; ++l) {
        float4 wv = wh[l], cv = wc[l];
#pragma unroll
        for (int r = 0; r < 8; ++r) {
            float4 zv = ((float4*)zs)[r * (Lz / 4) + l];
            ah[r] += zv.x * wv.x + zv.y * wv.y + zv.z * wv.z + zv.w * wv.w;
            ac[r] += zv.x * cv.x + zv.y * cv.y + zv.z * cv.z + zv.w * cv.w;
        }
    }
    float bhv = bh[k], bcv = bc[k];
#pragma unroll
    for (int r = 0; r < 8; ++r) {
        int b = b0 + r;
        float hv = ah[r] + bhv, cv = ac[r] + bcv;
        g_cT1[(size_t)k * Bsz + b] = cv;
        g_cT2[(size_t)k * Bsz + b] = cv;
        __nv_bfloat16 hh = __float2bfloat16(hv);
        __nv_bfloat16 hl = __float2bfloat16(hv - __bfloat162float(hh));
        g_P0h[0][(size_t)b * KB0 + Od + k] = hh;
        g_P0l[0][(size_t)b * KB0 + Od + k] = hl;
        g_P1h[0][(size_t)b * KB1 + Hd + k] = hh;
        g_P1l[0][(size_t)b * KB1 + Hd + k] = hl;
    }
    if (blockIdx.x == 0 && threadIdx.x < 64) {
        int o = threadIdx.x;
        __nv_bfloat16 zz = __float2bfloat16(0.f);
#pragma unroll
        for (int r = 0; r < 8; ++r) {
            int b = b0 + r;
            g_P0h[0][(size_t)b * KB0 + o] = zz;
            g_P0l[0][(size_t)b * KB0 + o] = zz;
        }
    }
}

// ---------------- Gzp = z @ Wzp.T + b0p (fp32, exact, step-invariant) ----------------
__global__ void gz_gemm(const float* __restrict__ z)
{
    __shared__ float zs[8 * Lz];
    int b0 = blockIdx.y * 8;
    for (int i = threadIdx.x; i < 8 * Lz / 4; i += 128)
        ((float4*)zs)[i] = ((const float4*)(z + (size_t)b0 * Lz))[i];
    __syncthreads();
    int n = blockIdx.x * 128 + threadIdx.x;
    const float4* w = (const float4*)(g_Wzp + (size_t)n * Lz);
    float acc[8] = {0};
#pragma unroll 8
    for (int l = 0; l < Lz / 4; ++l) {
        float4 wv = w[l];
#pragma unroll
        for (int r = 0; r < 8; ++r) {
            float4 zv = ((float4*)zs)[r * (Lz / 4) + l];
            acc[r] += zv.x * wv.x + zv.y * wv.y + zv.z * wv.z + zv.w * wv.w;
        }
    }
    float bb = g_b0p[n];
#pragma unroll
    for (int r = 0; r < 8; ++r)
        g_Gzp[(size_t)(b0 + r) * G4 + n] = acc[r] + bb;
}

// ---------------- dedup 3-pass HMMA GEMM (128x64, BK=64, 256 CTAs, 2 CTA/SM) ----------------
// acc = Ah@Wh + Ah@Wl + Al@Wh   (AlWl dropped; ~2^-17 relative)
struct EpiDst { __nv_bfloat16 *hi, *lo; int stride; };

__global__ __launch_bounds__(256, 2) void lstm_mma(
    const __nv_bfloat16* __restrict__ actH, const __nv_bfloat16* __restrict__ actL,
    int K, int nch,
    const __nv_bfloat16* __restrict__ WH, const __nv_bfloat16* __restrict__ WL,
    const float* __restrict__ initT, const float* __restrict__ bias,
    float* __restrict__ cT,
    EpiDst e0, EpiDst e1, float* __restrict__ h32)
{
    extern __shared__ char smem[];
    uint32_t sbase = s2u(smem);
    int tid = threadIdx.x;
    int n0 = blockIdx.x * 64, m0 = blockIdx.y * 128;
    int warp = tid >> 5, lane = tid & 31;
    int wm = warp >> 1, wn = warp & 1;      // 4 x 2 warp grid, warp tile 32 x 32
    int gid = lane >> 2, tid2 = lane & 3;

    float acc[2][4][4];
#pragma unroll
    for (int mi = 0; mi < 2; ++mi)
#pragma unroll
        for (int nj = 0; nj < 4; ++nj)
#pragma unroll
            for (int q = 0; q < 4; ++q) acc[mi][nj][q] = 0.f;

    int ldRow = tid >> 3, ldGrp = tid & 7;   // 32 rows per load pass
    size_t rowK = (size_t)ldRow * K;
    size_t step32 = (size_t)32 * K;

    // per-thread global bases (chunk 0); advance by BK each chunk
    const __nv_bfloat16* pah = actH + (size_t)m0 * K + rowK + ldGrp * 8;
    const __nv_bfloat16* pal = actL + (size_t)m0 * K + rowK + ldGrp * 8;
    const __nv_bfloat16* pwh = WH + (size_t)n0 * K + rowK + ldGrp * 8;
    const __nv_bfloat16* pwl = WL + (size_t)n0 * K + rowK + ldGrp * 8;

    // ldmatrix per-lane base offsets (bytes within a region) — validated mapping
    uint32_t aOff = (uint32_t)(wm * 32 + (lane & 15)) * ROWB + ((lane >> 4) * 16);
    uint32_t bOff = (uint32_t)(wn * 32 + (lane & 7) + ((lane >> 4) * 8)) * ROWB
                  + (((lane >> 3) & 1) * 16);
    uint32_t ldDst = (uint32_t)ldRow * ROWB + ldGrp * 16;

#define LOAD_CHUNK(CH, BUF) {                                                     \
        uint32_t st = sbase + (BUF) * STG + ldDst;                                \
        size_t go = (size_t)(CH) * BK;                                            \
        _Pragma("unroll")                                                         \
        for (int j = 0; j < 4; ++j) {                                             \
            cp16(st + j * 32 * ROWB, pah + go + j * step32);                      \
            cp16(st + OFF_AL + j * 32 * ROWB, pal + go + j * step32);             \
        }                                                                         \
        _Pragma("unroll")                                                         \
        for (int j = 0; j < 2; ++j) {                                             \
            cp16(st + OFF_WH + j * 32 * ROWB, pwh + go + j * step32);             \
            cp16(st + OFF_WL + j * 32 * ROWB, pwl + go + j * step32);             \
        }                                                                         \
        cp_commit();                                                              \
    }

    LOAD_CHUNK(0, 0)
    for (int ch = 0; ch < nch; ++ch) {
        int buf = ch & 1;
        cp_wait0();
        __syncthreads();
        if (ch + 1 < nch) LOAD_CHUNK(ch + 1, buf ^ 1)

        uint32_t st = sbase + buf * STG;
#pragma unroll
        for (int p = 0; p < 3; ++p) {
            uint32_t aB = st + (p == 2 ? OFF_AL : 0u) + aOff;               // Ah,Ah,Al
            uint32_t bB = st + (p == 1 ? OFF_WL : (uint32_t)OFF_WH) + bOff; // Wh,Wl,Wh
#pragma unroll
            for (int ks = 0; ks < 4; ++ks) {
                uint32_t Af[2][4], Bf[2][4];
#pragma unroll
                for (int mi = 0; mi < 2; ++mi) ldsm4(Af[mi], aB + mi * 16 * ROWB + ks * 32);
#pragma unroll
                for (int q = 0; q < 2; ++q)    ldsm4(Bf[q], bB + q * 16 * ROWB + ks * 32);
#pragma unroll
                for (int mi = 0; mi < 2; ++mi)
#pragma unroll
                    for (int q = 0; q < 2; ++q) {
                        mma16816(acc[mi][2 * q],     Af[mi], &Bf[q][0]);
                        mma16816(acc[mi][2 * q + 1], Af[mi], &Bf[q][2]);
                    }
            }
        }
    }
#undef LOAD_CHUNK
    __syncthreads();   // all ldsm done before smem reuse below

    // ---- epilogue: 2 passes of 128 rows x 32 gate cols through SMEM ----
    float* gbuf = (float*)smem;
    const int GP = 36;
    for (int nq = 0; nq < 2; ++nq) {
        if (wn == nq) {
#pragma unroll
            for (int mi = 0; mi < 2; ++mi)
#pragma unroll
                for (int nj = 0; nj < 4; ++nj) {
                    int r = wm * 32 + mi * 16 + gid;
                    int cl = nj * 8 + tid2 * 2;
                    gbuf[r * GP + cl]           = acc[mi][nj][0];
                    gbuf[r * GP + cl + 1]       = acc[mi][nj][1];
                    gbuf[(r + 8) * GP + cl]     = acc[mi][nj][2];
                    gbuf[(r + 8) * GP + cl + 1] = acc[mi][nj][3];
                }
        }
        __syncthreads();
#pragma unroll
        for (int idx = tid; idx < 1024; idx += 256) {
            int b = idx >> 3, g = idx & 7;
            int bg = m0 + b;
            float4 a4 = *(const float4*)&gbuf[b * GP + g * 4];
            float4 bb = initT
                ? *(const float4*)(initT + (size_t)bg * G4 + n0 + nq * 32 + g * 4)
                : *(const float4*)(bias + n0 + nq * 32 + g * 4);
            float i_ = fsig(a4.x + bb.x);
            float f_ = fsig(a4.y + bb.y);
            float g_ = ftanh(a4.z + bb.z);
            float o_ = fsig(a4.w + bb.w);
            int k = (n0 >> 2) + nq * 8 + g;
            float c = cT[(size_t)k * Bsz + bg];
            float cn = f_ * c + i_ * g_;
            cT[(size_t)k * Bsz + bg] = cn;
            float h = o_ * ftanh(cn);
            __nv_bfloat16 hh = __float2bfloat16(h);
            __nv_bfloat16 hl = __float2bfloat16(h - __bfloat162float(hh));
            e0.hi[(size_t)bg * e0.stride + k] = hh;
            e0.lo[(size_t)bg * e0.stride + k] = hl;
            if (e1.hi) {
                e1.hi[(size_t)bg * e1.stride + k] = hh;
                e1.lo[(size_t)bg * e1.stride + k] = hl;
            }
            if (h32) h32[(size_t)bg * Hd + k] = h;
        }
        __syncthreads();
    }
}

// ---------------- out = h2 @ Wout.T + bout -> d_out[:,t,:] + bf16 feedback ----------------
__global__ void out_proj(const float* __restrict__ h2, const float* __restrict__ Wout,
                         const float* __restrict__ bout, float* __restrict__ dout, int t,
                         __nv_bfloat16* __restrict__ PnH, __nv_bfloat16* __restrict__ PnL)
{
    __shared__ float hs[Hd];
    int b = blockIdx.x, o = threadIdx.x;
    for (int i = o; i < Hd / 4; i += 64)
        ((float4*)hs)[i] = ((const float4*)(h2 + (size_t)b * Hd))[i];
    __syncthreads();
    const float4* w = (const float4*)(Wout + (size_t)o * Hd);
    float acc = 0.f;
#pragma unroll 8
    for (int i = 0; i < Hd / 4; ++i) {
        float4 wv = w[i], hv = ((float4*)hs)[i];
        acc += wv.x * hv.x + wv.y * hv.y + wv.z * hv.z + wv.w * hv.w;
    }
    acc += bout[o];
    __nv_bfloat16 hh = __float2bfloat16(acc);
    PnH[(size_t)b * KB0 + o] = hh;
    PnL[(size_t)b * KB0 + o] = __float2bfloat16(acc - __bfloat162float(hh));
    dout[(size_t)b * Sq * Od + (size_t)t * Od + o] = acc;
}

// ---------------- host ----------------
extern "C" void kernel_launch(void* const* d_in, const int* in_sizes, int n_in,
                              void* d_out, int out_size)
{
    const float* z    = (const float*)d_in[0];
    const float* Wh   = (const float*)d_in[1];
    const float* bh   = (const float*)d_in[2];
    const float* Wc   = (const float*)d_in[3];
    const float* bc   = (const float*)d_in[4];
    const float* Wih0 = (const float*)d_in[5];
    const float* Whh0 = (const float*)d_in[6];
    const float* bih0 = (const float*)d_in[7];
    const float* bhh0 = (const float*)d_in[8];
    const float* Wih1 = (const float*)d_in[9];
    const float* Whh1 = (const float*)d_in[10];
    const float* bih1 = (const float*)d_in[11];
    const float* bhh1 = (const float*)d_in[12];
    const float* Wout = (const float*)d_in[13];
    const float* bout = (const float*)d_in[14];
    float* out = (float*)d_out;

    __nv_bfloat16 *p_W0h, *p_W0l, *p_W1h, *p_W1l, *p_P0h, *p_P0l, *p_P1h, *p_P1l;
    float *p_Gzp, *p_b1p, *p_cT1, *p_cT2, *p_h2f;
    cudaGetSymbolAddress((void**)&p_W0h, g_W0h);
    cudaGetSymbolAddress((void**)&p_W0l, g_W0l);
    cudaGetSymbolAddress((void**)&p_W1h, g_W1h);
    cudaGetSymbolAddress((void**)&p_W1l, g_W1l);
    cudaGetSymbolAddress((void**)&p_P0h, g_P0h);
    cudaGetSymbolAddress((void**)&p_P0l, g_P0l);
    cudaGetSymbolAddress((void**)&p_P1h, g_P1h);
    cudaGetSymbolAddress((void**)&p_P1l, g_P1l);
    cudaGetSymbolAddress((void**)&p_Gzp, g_Gzp);
    cudaGetSymbolAddress((void**)&p_b1p, g_b1p);
    cudaGetSymbolAddress((void**)&p_cT1, g_cT1);
    cudaGetSymbolAddress((void**)&p_cT2, g_cT2);
    cudaGetSymbolAddress((void**)&p_h2f, g_h2f);

    cudaFuncSetAttribute(lstm_mma, cudaFuncAttributeMaxDynamicSharedMemorySize, SMEM_TOTAL);

    pack_weights<<<G4, 256>>>(Wih0, Whh0, bih0, bhh0, Wih1, Whh1, bih1, bhh1);
    init_hc<<<dim3(Hd / 128, Bsz / 8), 128>>>(z, Wh, bh, Wc, bc);
    gz_gemm<<<dim3(G4 / 128, Bsz / 8), 128>>>(z);

    dim3 gg(G4 / 64, Bsz / 128);     // 64 x 4 = 256 CTAs
    const size_t P0sz = (size_t)Bsz * KB0, P1sz = (size_t)Bsz * KB1;
    for (int t = 0; t < Sq; ++t) {
        int cur = t & 1, nxt = cur ^ 1;
        __nv_bfloat16 *P0hc = p_P0h + cur * P0sz, *P0lc = p_P0l + cur * P0sz;
        __nv_bfloat16 *P0hn = p_P0h + nxt * P0sz, *P0ln = p_P0l + nxt * P0sz;
        __nv_bfloat16 *P1hc = p_P1h + cur * P1sz, *P1lc = p_P1l + cur * P1sz;
        __nv_bfloat16 *P1hn = p_P1h + nxt * P1sz, *P1ln = p_P1l + nxt * P1sz;

        // layer 0: gates = Gzp + [fb h1] @ W0.T  (3-term split in-kernel)
        EpiDst e0{P1hc + 0, P1lc + 0, KB1};        // h1n -> layer1 panel (this step)
        EpiDst e1{P0hn + Od, P0ln + Od, KB0};      // h1n -> layer0 panel (next step)
        lstm_mma<<<gg, 256, SMEM_TOTAL>>>(P0hc, P0lc, KB0, KB0 / BK, p_W0h, p_W0l,
                                          p_Gzp, nullptr, p_cT1, e0, e1, nullptr);

        // layer 1: gates = b1p + [h1n h2] @ W1.T
        EpiDst f0{P1hn + Hd, P1ln + Hd, KB1};      // h2 -> layer1 panel (next step)
        EpiDst f1{nullptr, nullptr, 0};
        lstm_mma<<<gg, 256, SMEM_TOTAL>>>(P1hc, P1lc, KB1, KB1 / BK, p_W1h, p_W1l,
                                          nullptr, p_b1p, p_cT2, f0, f1, p_h2f);

        out_proj<<<Bsz, 64>>>(p_h2f, Wout, bout, out, t, P0hn, P0ln);
    }
}

// round 17
// speedup vs baseline: 1.3381x; 1.0146x over previous
#include <cuda_runtime.h>
#include <cuda_bf16.h>
#include <cstdint>

constexpr int Bsz = 512, Lz = 128, Hd = 1024, Od = 64, Sq = 256;
constexpr int G4 = 4096, IN0 = 192;
constexpr int KB0 = Od + Hd;      // 1088 = 17*64  (layer0 base K)
constexpr int KB1 = 2 * Hd;       // 2048 = 32*64  (layer1 base K)
constexpr size_t BH = (size_t)Bsz * Hd;

constexpr int BK = 64;
constexpr int ROWB = 144;                 // 128B data + 16B pad
constexpr int RA = 128 * ROWB;            // A region: 18432 B
constexpr int RB = 64 * ROWB;             // W region: 9216 B
constexpr int OFF_AL = RA;                // Al
constexpr int OFF_WH = 2 * RA;            // Wh
constexpr int OFF_WL = 2 * RA + RB;       // Wl
constexpr int STG = 2 * RA + 2 * RB;      // 55296 B per stage
constexpr int SMEM_TOTAL = 2 * STG;       // 110592 B -> 2 CTAs/SM

// ---------------- device scratch ----------------
__device__ __align__(1024) __nv_bfloat16 g_W0h[(size_t)G4 * KB0];
__device__ __align__(1024) __nv_bfloat16 g_W0l[(size_t)G4 * KB0];
__device__ __align__(1024) __nv_bfloat16 g_W1h[(size_t)G4 * KB1];
__device__ __align__(1024) __nv_bfloat16 g_W1l[(size_t)G4 * KB1];
__device__ __align__(1024) __nv_bfloat16 g_P0h[2][(size_t)Bsz * KB0];  // [fb | h1]
__device__ __align__(1024) __nv_bfloat16 g_P0l[2][(size_t)Bsz * KB0];
__device__ __align__(1024) __nv_bfloat16 g_P1h[2][(size_t)Bsz * KB1];  // [h1n | h2]
__device__ __align__(1024) __nv_bfloat16 g_P1l[2][(size_t)Bsz * KB1];
__device__ float g_Wzp[(size_t)G4 * Lz];
__device__ float g_b0p[G4];
__device__ float g_b1p[G4];
__device__ float g_Gzp[(size_t)Bsz * G4];
__device__ float g_cT1[BH];     // c state transposed [k][b]
__device__ float g_cT2[BH];
__device__ float g_h2f[BH];

__device__ __forceinline__ float fsig(float x) { return 1.f / (1.f + __expf(-x)); }
__device__ __forceinline__ float ftanh(float x) {
    float e = __expf(2.f * x);
    return (e - 1.f) * (1.f / (e + 1.f));
}

__device__ __forceinline__ uint32_t s2u(const void* p) {
    uint32_t a;
    asm("{ .reg .u64 t; cvta.to.shared.u64 t, %1; cvt.u32.u64 %0, t; }" : "=r"(a) : "l"(p));
    return a;
}
__device__ __forceinline__ void cp16(uint32_t d, const void* s) {
    asm volatile("cp.async.cg.shared.global [%0], [%1], 16;" :: "r"(d), "l"(s) : "memory");
}
__device__ __forceinline__ void cp_commit() { asm volatile("cp.async.commit_group;" ::: "memory"); }
__device__ __forceinline__ void cp_wait0()  { asm volatile("cp.async.wait_group 0;" ::: "memory"); }

__device__ __forceinline__ void ldsm4(uint32_t* r, uint32_t addr) {
    asm volatile("ldmatrix.sync.aligned.m8n8.x4.shared.b16 {%0,%1,%2,%3}, [%4];"
                 : "=r"(r[0]), "=r"(r[1]), "=r"(r[2]), "=r"(r[3]) : "r"(addr));
}
__device__ __forceinline__ void mma16816(float* c, const uint32_t* a, const uint32_t* b) {
    asm volatile(
        "mma.sync.aligned.m16n8k16.row.col.f32.bf16.bf16.f32 "
        "{%0,%1,%2,%3}, {%4,%5,%6,%7}, {%8,%9}, {%0,%1,%2,%3};"
        : "+f"(c[0]), "+f"(c[1]), "+f"(c[2]), "+f"(c[3])
        : "r"(a[0]), "r"(a[1]), "r"(a[2]), "r"(a[3]), "r"(b[0]), "r"(b[1]));
}

// ---------------- prepass: permute(g*H+k -> 4k+g) + bf16 hi/lo split ----------------
__global__ void pack_weights(const float* __restrict__ Wih0, const float* __restrict__ Whh0,
                             const float* __restrict__ bih0, const float* __restrict__ bhh0,
                             const float* __restrict__ Wih1, const float* __restrict__ Whh1,
                             const float* __restrict__ bih1, const float* __restrict__ bhh1)
{
    int n = blockIdx.x, k = n >> 2, g = n & 3, src = g * Hd + k;
    for (int j = threadIdx.x; j < KB0; j += 256) {
        float w = (j < Od) ? Wih0[(size_t)src * IN0 + Lz + j] : Whh0[(size_t)src * Hd + (j - Od)];
        __nv_bfloat16 h = __float2bfloat16(w);
        g_W0h[(size_t)n * KB0 + j] = h;
        g_W0l[(size_t)n * KB0 + j] = __float2bfloat16(w - __bfloat162float(h));
    }
    for (int j = threadIdx.x; j < KB1; j += 256) {
        float w = (j < Hd) ? Wih1[(size_t)src * Hd + j] : Whh1[(size_t)src * Hd + (j - Hd)];
        __nv_bfloat16 h = __float2bfloat16(w);
        g_W1h[(size_t)n * KB1 + j] = h;
        g_W1l[(size_t)n * KB1 + j] = __float2bfloat16(w - __bfloat162float(h));
    }
    for (int j = threadIdx.x; j < Lz; j += 256)
        g_Wzp[(size_t)n * Lz + j] = Wih0[(size_t)src * IN0 + j];
    if (threadIdx.x == 0) {
        g_b0p[n] = bih0[src] + bhh0[src];
        g_b1p[n] = bih1[src] + bhh1[src];
    }
}

// ---------------- init: h0/c0 projections -> panels / cT; zero fb slots ----------------
__global__ void init_hc(const float* __restrict__ z,
                        const float* __restrict__ Wh, const float* __restrict__ bh,
                        const float* __restrict__ Wc, const float* __restrict__ bc)
{
    __shared__ float zs[8 * Lz];
    int b0 = blockIdx.y * 8;
    for (int i = threadIdx.x; i < 8 * Lz / 4; i += 128)
        ((float4*)zs)[i] = ((const float4*)(z + (size_t)b0 * Lz))[i];
    __syncthreads();
    int k = blockIdx.x * 128 + threadIdx.x;
    const float4* wh = (const float4*)(Wh + (size_t)k * Lz);
    const float4* wc = (const float4*)(Wc + (size_t)k * Lz);
    float ah[8] = {0}, ac[8] = {0};
#pragma unroll 8
    for (int l = 0; l < Lz / 4; ++l) {
        float4 wv = wh[l], cv = wc[l];
#pragma unroll
        for (int r = 0; r < 8; ++r) {
            float4 zv = ((float4*)zs)[r * (Lz / 4) + l];
            ah[r] += zv.x * wv.x + zv.y * wv.y + zv.z * wv.z + zv.w * wv.w;
            ac[r] += zv.x * cv.x + zv.y * cv.y + zv.z * cv.z + zv.w * cv.w;
        }
    }
    float bhv = bh[k], bcv = bc[k];
#pragma unroll
    for (int r = 0; r < 8; ++r) {
        int b = b0 + r;
        float hv = ah[r] + bhv, cv = ac[r] + bcv;
        g_cT1[(size_t)k * Bsz + b] = cv;
        g_cT2[(size_t)k * Bsz + b] = cv;
        __nv_bfloat16 hh = __float2bfloat16(hv);
        __nv_bfloat16 hl = __float2bfloat16(hv - __bfloat162float(hh));
        g_P0h[0][(size_t)b * KB0 + Od + k] = hh;
        g_P0l[0][(size_t)b * KB0 + Od + k] = hl;
        g_P1h[0][(size_t)b * KB1 + Hd + k] = hh;
        g_P1l[0][(size_t)b * KB1 + Hd + k] = hl;
    }
    if (blockIdx.x == 0 && threadIdx.x < 64) {
        int o = threadIdx.x;
        __nv_bfloat16 zz = __float2bfloat16(0.f);
#pragma unroll
        for (int r = 0; r < 8; ++r) {
            int b = b0 + r;
            g_P0h[0][(size_t)b * KB0 + o] = zz;
            g_P0l[0][(size_t)b * KB0 + o] = zz;
        }
    }
}

// ---------------- Gzp = z @ Wzp.T + b0p (fp32, exact, step-invariant) ----------------
__global__ void gz_gemm(const float* __restrict__ z)
{
    __shared__ float zs[8 * Lz];
    int b0 = blockIdx.y * 8;
    for (int i = threadIdx.x; i < 8 * Lz / 4; i += 128)
        ((float4*)zs)[i] = ((const float4*)(z + (size_t)b0 * Lz))[i];
    __syncthreads();
    int n = blockIdx.x * 128 + threadIdx.x;
    const float4* w = (const float4*)(g_Wzp + (size_t)n * Lz);
    float acc[8] = {0};
#pragma unroll 8
    for (int l = 0; l < Lz / 4; ++l) {
        float4 wv = w[l];
#pragma unroll
        for (int r = 0; r < 8; ++r) {
            float4 zv = ((float4*)zs)[r * (Lz / 4) + l];
            acc[r] += zv.x * wv.x + zv.y * wv.y + zv.z * wv.z + zv.w * wv.w;
        }
    }
    float bb = g_b0p[n];
#pragma unroll
    for (int r = 0; r < 8; ++r)
        g_Gzp[(size_t)(b0 + r) * G4 + n] = acc[r] + bb;
}

// ---------------- dedup fused-pass HMMA GEMM (128x64, BK=64, 2 CTA/SM) ----------------
// acc = Ah@Wh + Ah@Wl + Al@Wh   (AlWl dropped; ~2^-17 relative)
// fragments loaded ONCE per ks: 8 ldsm -> 24 mma
struct EpiDst { __nv_bfloat16 *hi, *lo; int stride; };

__global__ __launch_bounds__(256, 2) void lstm_mma(
    const __nv_bfloat16* __restrict__ actH, const __nv_bfloat16* __restrict__ actL,
    int K, int nch,
    const __nv_bfloat16* __restrict__ WH, const __nv_bfloat16* __restrict__ WL,
    const float* __restrict__ initT, const float* __restrict__ bias,
    float* __restrict__ cT,
    EpiDst e0, EpiDst e1, float* __restrict__ h32)
{
    extern __shared__ char smem[];
    uint32_t sbase = s2u(smem);
    int tid = threadIdx.x;
    int n0 = blockIdx.x * 64, m0 = blockIdx.y * 128;
    int warp = tid >> 5, lane = tid & 31;
    int wm = warp >> 1, wn = warp & 1;      // 4 x 2 warp grid, warp tile 32 x 32
    int gid = lane >> 2, tid2 = lane & 3;

    float acc[2][4][4];
#pragma unroll
    for (int mi = 0; mi < 2; ++mi)
#pragma unroll
        for (int nj = 0; nj < 4; ++nj)
#pragma unroll
            for (int q = 0; q < 4; ++q) acc[mi][nj][q] = 0.f;

    int ldRow = tid >> 3, ldGrp = tid & 7;   // 32 rows per load pass
    size_t rowK = (size_t)ldRow * K;
    size_t step32 = (size_t)32 * K;

    const __nv_bfloat16* pah = actH + (size_t)m0 * K + rowK + ldGrp * 8;
    const __nv_bfloat16* pal = actL + (size_t)m0 * K + rowK + ldGrp * 8;
    const __nv_bfloat16* pwh = WH + (size_t)n0 * K + rowK + ldGrp * 8;
    const __nv_bfloat16* pwl = WL + (size_t)n0 * K + rowK + ldGrp * 8;

    // ldmatrix per-lane base offsets (bytes within a region) — validated mapping
    uint32_t aOff = (uint32_t)(wm * 32 + (lane & 15)) * ROWB + ((lane >> 4) * 16);
    uint32_t bOff = (uint32_t)(wn * 32 + (lane & 7) + ((lane >> 4) * 8)) * ROWB
                  + (((lane >> 3) & 1) * 16);
    uint32_t ldDst = (uint32_t)ldRow * ROWB + ldGrp * 16;

#define LOAD_CHUNK(CH, BUF) {                                                     \
        uint32_t st = sbase + (BUF) * STG + ldDst;                                \
        size_t go = (size_t)(CH) * BK;                                            \
        _Pragma("unroll")                                                         \
        for (int j = 0; j < 4; ++j) {                                             \
            cp16(st + j * 32 * ROWB, pah + go + j * step32);                      \
            cp16(st + OFF_AL + j * 32 * ROWB, pal + go + j * step32);             \
        }                                                                         \
        _Pragma("unroll")                                                         \
        for (int j = 0; j < 2; ++j) {                                             \
            cp16(st + OFF_WH + j * 32 * ROWB, pwh + go + j * step32);             \
            cp16(st + OFF_WL + j * 32 * ROWB, pwl + go + j * step32);             \
        }                                                                         \
        cp_commit();                                                              \
    }

    LOAD_CHUNK(0, 0)
    for (int ch = 0; ch < nch; ++ch) {
        int buf = ch & 1;
        cp_wait0();
        __syncthreads();
        if (ch + 1 < nch) LOAD_CHUNK(ch + 1, buf ^ 1)

        uint32_t aB = sbase + buf * STG + aOff;
        uint32_t bB = sbase + buf * STG + bOff;
#pragma unroll
        for (int ks = 0; ks < 4; ++ks) {
            uint32_t Ah[2][4], Al2[2][4], Bh[2][4], Bl[2][4];
#pragma unroll
            for (int mi = 0; mi < 2; ++mi) {
                ldsm4(Ah[mi],  aB + mi * 16 * ROWB + ks * 32);
                ldsm4(Al2[mi], aB + OFF_AL + mi * 16 * ROWB + ks * 32);
            }
#pragma unroll
            for (int q = 0; q < 2; ++q) {
                ldsm4(Bh[q], bB + OFF_WH + q * 16 * ROWB + ks * 32);
                ldsm4(Bl[q], bB + OFF_WL + q * 16 * ROWB + ks * 32);
            }
#pragma unroll
            for (int mi = 0; mi < 2; ++mi)
#pragma unroll
                for (int q = 0; q < 2; ++q) {
                    mma16816(acc[mi][2 * q],     Ah[mi], &Bh[q][0]);
                    mma16816(acc[mi][2 * q + 1], Ah[mi], &Bh[q][2]);
                    mma16816(acc[mi][2 * q],     Ah[mi], &Bl[q][0]);
                    mma16816(acc[mi][2 * q + 1], Ah[mi], &Bl[q][2]);
                    mma16816(acc[mi][2 * q],     Al2[mi], &Bh[q][0]);
                    mma16816(acc[mi][2 * q + 1], Al2[mi], &Bh[q][2]);
                }
        }
    }
#undef LOAD_CHUNK
    __syncthreads();   // all ldsm done before smem reuse below

    // ---- epilogue: 2 passes of 128 rows x 32 gate cols through SMEM ----
    float* gbuf = (float*)smem;
    const int GP = 36;
    for (int nq = 0; nq < 2; ++nq) {
        if (wn == nq) {
#pragma unroll
            for (int mi = 0; mi < 2; ++mi)
#pragma unroll
                for (int nj = 0; nj < 4; ++nj) {
                    int r = wm * 32 + mi * 16 + gid;
                    int cl = nj * 8 + tid2 * 2;
                    gbuf[r * GP + cl]           = acc[mi][nj][0];
                    gbuf[r * GP + cl + 1]       = acc[mi][nj][1];
                    gbuf[(r + 8) * GP + cl]     = acc[mi][nj][2];
                    gbuf[(r + 8) * GP + cl + 1] = acc[mi][nj][3];
                }
        }
        __syncthreads();
#pragma unroll
        for (int idx = tid; idx < 1024; idx += 256) {
            int b = idx >> 3, g = idx & 7;
            int bg = m0 + b;
            float4 a4 = *(const float4*)&gbuf[b * GP + g * 4];
            float4 bb = initT
                ? *(const float4*)(initT + (size_t)bg * G4 + n0 + nq * 32 + g * 4)
                : *(const float4*)(bias + n0 + nq * 32 + g * 4);
            float i_ = fsig(a4.x + bb.x);
            float f_ = fsig(a4.y + bb.y);
            float g_ = ftanh(a4.z + bb.z);
            float o_ = fsig(a4.w + bb.w);
            int k = (n0 >> 2) + nq * 8 + g;
            float c = cT[(size_t)k * Bsz + bg];
            float cn = f_ * c + i_ * g_;
            cT[(size_t)k * Bsz + bg] = cn;
            float h = o_ * ftanh(cn);
            __nv_bfloat16 hh = __float2bfloat16(h);
            __nv_bfloat16 hl = __float2bfloat16(h - __bfloat162float(hh));
            e0.hi[(size_t)bg * e0.stride + k] = hh;
            e0.lo[(size_t)bg * e0.stride + k] = hl;
            if (e1.hi) {
                e1.hi[(size_t)bg * e1.stride + k] = hh;
                e1.lo[(size_t)bg * e1.stride + k] = hl;
            }
            if (h32) h32[(size_t)bg * Hd + k] = h;
        }
        __syncthreads();
    }
}

// ---------------- out = h2 @ Wout.T + bout -> d_out[:,t,:] + bf16 feedback ----------------
__global__ void out_proj(const float* __restrict__ h2, const float* __restrict__ Wout,
                         const float* __restrict__ bout, float* __restrict__ dout, int t,
                         __nv_bfloat16* __restrict__ PnH, __nv_bfloat16* __restrict__ PnL)
{
    __shared__ float hs[Hd];
    int b = blockIdx.x, o = threadIdx.x;
    for (int i = o; i < Hd / 4; i += 64)
        ((float4*)hs)[i] = ((const float4*)(h2 + (size_t)b * Hd))[i];
    __syncthreads();
    const float4* w = (const float4*)(Wout + (size_t)o * Hd);
    float acc = 0.f;
#pragma unroll 8
    for (int i = 0; i < Hd / 4; ++i) {
        float4 wv = w[i], hv = ((float4*)hs)[i];
        acc += wv.x * hv.x + wv.y * hv.y + wv.z * hv.z + wv.w * hv.w;
    }
    acc += bout[o];
    __nv_bfloat16 hh = __float2bfloat16(acc);
    PnH[(size_t)b * KB0 + o] = hh;
    PnL[(size_t)b * KB0 + o] = __float2bfloat16(acc - __bfloat162float(hh));
    dout[(size_t)b * Sq * Od + (size_t)t * Od + o] = acc;
}

// ---------------- host ----------------
extern "C" void kernel_launch(void* const* d_in, const int* in_sizes, int n_in,
                              void* d_out, int out_size)
{
    const float* z    = (const float*)d_in[0];
    const float* Wh   = (const float*)d_in[1];
    const float* bh   = (const float*)d_in[2];
    const float* Wc   = (const float*)d_in[3];
    const float* bc   = (const float*)d_in[4];
    const float* Wih0 = (const float*)d_in[5];
    const float* Whh0 = (const float*)d_in[6];
    const float* bih0 = (const float*)d_in[7];
    const float* bhh0 = (const float*)d_in[8];
    const float* Wih1 = (const float*)d_in[9];
    const float* Whh1 = (const float*)d_in[10];
    const float* bih1 = (const float*)d_in[11];
    const float* bhh1 = (const float*)d_in[12];
    const float* Wout = (const float*)d_in[13];
    const float* bout = (const float*)d_in[14];
    float* out = (float*)d_out;

    __nv_bfloat16 *p_W0h, *p_W0l, *p_W1h, *p_W1l, *p_P0h, *p_P0l, *p_P1h, *p_P1l;
    float *p_Gzp, *p_b1p, *p_cT1, *p_cT2, *p_h2f;
    cudaGetSymbolAddress((void**)&p_W0h, g_W0h);
    cudaGetSymbolAddress((void**)&p_W0l, g_W0l);
    cudaGetSymbolAddress((void**)&p_W1h, g_W1h);
    cudaGetSymbolAddress((void**)&p_W1l, g_W1l);
    cudaGetSymbolAddress((void**)&p_P0h, g_P0h);
    cudaGetSymbolAddress((void**)&p_P0l, g_P0l);
    cudaGetSymbolAddress((void**)&p_P1h, g_P1h);
    cudaGetSymbolAddress((void**)&p_P1l, g_P1l);
    cudaGetSymbolAddress((void**)&p_Gzp, g_Gzp);
    cudaGetSymbolAddress((void**)&p_b1p, g_b1p);
    cudaGetSymbolAddress((void**)&p_cT1, g_cT1);
    cudaGetSymbolAddress((void**)&p_cT2, g_cT2);
    cudaGetSymbolAddress((void**)&p_h2f, g_h2f);

    cudaFuncSetAttribute(lstm_mma, cudaFuncAttributeMaxDynamicSharedMemorySize, SMEM_TOTAL);

    pack_weights<<<G4, 256>>>(Wih0, Whh0, bih0, bhh0, Wih1, Whh1, bih1, bhh1);
    init_hc<<<dim3(Hd / 128, Bsz / 8), 128>>>(z, Wh, bh, Wc, bc);
    gz_gemm<<<dim3(G4 / 128, Bsz / 8), 128>>>(z);

    dim3 gg(G4 / 64, Bsz / 128);     // 64 x 4 = 256 CTAs
    const size_t P0sz = (size_t)Bsz * KB0, P1sz = (size_t)Bsz * KB1;
    for (int t = 0; t < Sq; ++t) {
        int cur = t & 1, nxt = cur ^ 1;
        __nv_bfloat16 *P0hc = p_P0h + cur * P0sz, *P0lc = p_P0l + cur * P0sz;
        __nv_bfloat16 *P0hn = p_P0h + nxt * P0sz, *P0ln = p_P0l + nxt * P0sz;
        __nv_bfloat16 *P1hc = p_P1h + cur * P1sz, *P1lc = p_P1l + cur * P1sz;
        __nv_bfloat16 *P1hn = p_P1h + nxt * P1sz, *P1ln = p_P1l + nxt * P1sz;

        // layer 0: gates = Gzp + [fb h1] @ W0.T  (3-term split in-kernel)
        EpiDst e0{P1hc + 0, P1lc + 0, KB1};        // h1n -> layer1 panel (this step)
        EpiDst e1{P0hn + Od, P0ln + Od, KB0};      // h1n -> layer0 panel (next step)
        lstm_mma<<<gg, 256, SMEM_TOTAL>>>(P0hc, P0lc, KB0, KB0 / BK, p_W0h, p_W0l,
                                          p_Gzp, nullptr, p_cT1, e0, e1, nullptr);

        // layer 1: gates = b1p + [h1n h2] @ W1.T
        EpiDst f0{P1hn + Hd, P1ln + Hd, KB1};      // h2 -> layer1 panel (next step)
        EpiDst f1{nullptr, nullptr, 0};
        lstm_mma<<<gg, 256, SMEM_TOTAL>>>(P1hc, P1lc, KB1, KB1 / BK, p_W1h, p_W1l,
                                          nullptr, p_b1p, p_cT2, f0, f1, p_h2f);

        out_proj<<<Bsz, 64>>>(p_h2f, Wout, bout, out, t, P0hn, P0ln);
    }
}